// round 14
// baseline (speedup 1.0000x reference)
#include <cuda_runtime.h>
#include <cuda_bf16.h>
#include <cuda_fp16.h>
#include <cstdint>

#define N_NODES 100000
#define N_EDGES 3200000
#define IN_DIM  512
#define HID     256
#define CLS     64

// ---- device scratch ----
__device__ __half g_w1t[HID * IN_DIM];            // W1^T fp16 [n=256][k=512]
__device__ __half g_w2t[CLS * HID];               // W2^T fp16 [n=64][k=256]
__device__ uint32_t g_xh[(size_t)N_NODES * 256];  // x fp16x2
__device__ uint32_t g_hh[(size_t)N_NODES * 128];  // H hi fp16x2
__device__ uint32_t g_hl[(size_t)N_NODES * 128];  // H lo fp16x2
__device__ float g_bufA[(size_t)N_NODES * CLS];   // fp32 state
__device__ float g_bufB[(size_t)N_NODES * CLS];
__device__ __half2 g_c16A[(size_t)N_NODES * 32];  // fp16 gather shadow
__device__ __half2 g_c16B[(size_t)N_NODES * 32];
__device__ int   g_rowptr[N_NODES + 1];

// ---- helpers ----
__device__ __forceinline__ uint32_t smem_u32(const void* p) {
    uint32_t a;
    asm("{ .reg .u64 t; cvta.to.shared.u64 t, %1; cvt.u32.u64 %0, t; }" : "=r"(a) : "l"(p));
    return a;
}
__device__ __forceinline__ uint32_t pk2h(float a, float b) {    // fp16x2
    uint16_t ha = __half_as_ushort(__float2half_rn(a));
    uint16_t hb = __half_as_ushort(__float2half_rn(b));
    return (uint32_t)ha | ((uint32_t)hb << 16);
}
__device__ __forceinline__ void ldsm4(uint32_t* r, uint32_t addr) {
    asm volatile("ldmatrix.sync.aligned.m8n8.x4.shared.b16 {%0,%1,%2,%3}, [%4];"
                 : "=r"(r[0]), "=r"(r[1]), "=r"(r[2]), "=r"(r[3]) : "r"(addr));
}
__device__ __forceinline__ void mma_f16(float* c, const uint32_t* a,
                                        uint32_t b0, uint32_t b1) {
    asm volatile(
        "mma.sync.aligned.m16n8k16.row.col.f32.f16.f16.f32 "
        "{%0,%1,%2,%3}, {%4,%5,%6,%7}, {%8,%9}, {%0,%1,%2,%3};"
        : "+f"(c[0]), "+f"(c[1]), "+f"(c[2]), "+f"(c[3])
        : "r"(a[0]), "r"(a[1]), "r"(a[2]), "r"(a[3]), "r"(b0), "r"(b1));
}
__device__ __forceinline__ void cpa16(uint32_t dst, const void* src, uint32_t sz) {
    asm volatile("cp.async.ca.shared.global [%0], [%1], 16, %2;"
                 :: "r"(dst), "l"(src), "r"(sz));
}
__device__ __forceinline__ void cpa_commit() { asm volatile("cp.async.commit_group;"); }
__device__ __forceinline__ void cpa_wait1()  { asm volatile("cp.async.wait_group 1;"); }
__device__ __forceinline__ void cpa_wait0()  { asm volatile("cp.async.wait_group 0;"); }

// ---- prep ----
__global__ void prep_w(const float* __restrict__ W1, const float* __restrict__ W2) {
    int idx = blockIdx.x * 256 + threadIdx.x;
    if (idx < HID * IN_DIM) {
        int n = idx >> 9, k = idx & 511;
        g_w1t[idx] = __float2half_rn(W1[k * HID + n]);
    }
    int j = idx - HID * IN_DIM;
    if (j >= 0 && j < CLS * HID) {
        int o = j >> 8, k = j & 255;
        g_w2t[j] = __float2half_rn(W2[k * CLS + o]);
    }
}
__global__ void prep_x(const float2* __restrict__ x2) {
    long i = (long)blockIdx.x * 256 + threadIdx.x;
    if (i >= (long)N_NODES * 256) return;
    float2 v = x2[i];
    g_xh[i] = pk2h(v.x, v.y);
}
__global__ void rowptr_kernel(const int* __restrict__ erow) {
    int r = blockIdx.x * 256 + threadIdx.x;
    if (r > N_NODES) return;
    int lo = 0, hi = N_EDGES;
    while (lo < hi) { int mid = (lo + hi) >> 1; if (erow[mid] < r) lo = mid + 1; else hi = mid; }
    g_rowptr[r] = lo;
}

// ======================= GEMM1 =======================
// H = relu(x@W1+b1), single-pass fp16. BM=128 BN=128, 2-stage cp.async, occ 2.
#define ST1 20480
#define SM1_BYTES (2 * ST1)
__device__ __forceinline__ void mlp1_fill(uint8_t* sm, int s, int kc, int tid,
                                          long grow0, int nbase) {
    const uint32_t so = (uint32_t)s * ST1;
    #pragma unroll
    for (int it = 0; it < 2; it++) {
        int i = tid + it * 256;
        int row = i >> 2, c = i & 3;
        long grow = grow0 + row;
        const uint32_t* src = g_xh + (grow < N_NODES ? grow * 256 : 0) + kc * 16 + c * 4;
        uint32_t dst = smem_u32(sm) + so + (uint32_t)(row * 80 + c * 16);
        cpa16(dst, src, grow < N_NODES ? 16u : 0u);
    }
    #pragma unroll
    for (int it = 0; it < 2; it++) {
        int i = tid + it * 256;
        int n = i >> 2, c = i & 3;
        const uint32_t* src = (const uint32_t*)g_w1t
                              + (long)(nbase + n) * 256 + kc * 16 + c * 4;
        uint32_t dst = smem_u32(sm) + so + (uint32_t)(10240 + n * 80 + c * 16);
        cpa16(dst, src, 16u);
    }
}
__global__ __launch_bounds__(256, 2)
void mlp1_kernel(const float* __restrict__ b1) {
    extern __shared__ uint8_t sm1[];
    const uint32_t sb = smem_u32(sm1);
    const int tid = threadIdx.x, lane = tid & 31, wid = tid >> 5;
    const int wm = wid >> 2, wn = wid & 3;
    const int mtile = blockIdx.x >> 1, nbase = (blockIdx.x & 1) * 128;
    const long grow0 = (long)mtile * 128;

    float acc[4][4][4];
    #pragma unroll
    for (int a = 0; a < 4; a++)
        #pragma unroll
        for (int b = 0; b < 4; b++)
            #pragma unroll
            for (int c = 0; c < 4; c++) acc[a][b][c] = 0.f;

    mlp1_fill(sm1, 0, 0, tid, grow0, nbase);
    cpa_commit();

    for (int kc = 0; kc < 16; kc++) {
        const int cur = kc & 1;
        if (kc + 1 < 16) { mlp1_fill(sm1, 1 - cur, kc + 1, tid, grow0, nbase); cpa_commit(); }
        if (kc + 1 < 16) cpa_wait1(); else cpa_wait0();
        __syncthreads();
        const uint32_t so = (uint32_t)cur * ST1;
        #pragma unroll
        for (int ks = 0; ks < 2; ks++) {
            const uint32_t colb = (uint32_t)((ks * 16 + (lane >> 4) * 8) * 2);
            uint32_t bb[2][4];
            #pragma unroll
            for (int g = 0; g < 2; g++) {
                int n = wn * 32 + g * 16 + (lane & 15);
                ldsm4(bb[g], sb + so + 10240 + (uint32_t)(n * 80) + colb);
            }
            #pragma unroll
            for (int mt = 0; mt < 4; mt++) {
                int r = wm * 64 + mt * 16 + (lane & 15);
                uint32_t ah[4];
                ldsm4(ah, sb + so + (uint32_t)(r * 80) + colb);
                #pragma unroll
                for (int g = 0; g < 2; g++) {
                    mma_f16(acc[mt][2 * g],     ah, bb[g][0], bb[g][2]);
                    mma_f16(acc[mt][2 * g + 1], ah, bb[g][1], bb[g][3]);
                }
            }
        }
        __syncthreads();
    }
    const int g = lane >> 2, t4 = lane & 3;
    #pragma unroll
    for (int mt = 0; mt < 4; mt++) {
        #pragma unroll
        for (int nt = 0; nt < 4; nt++) {
            int c = nbase + wn * 32 + nt * 8 + t4 * 2;
            float bb0 = __ldg(&b1[c]), bb1 = __ldg(&b1[c + 1]);
            #pragma unroll
            for (int h = 0; h < 2; h++) {
                long grow = grow0 + wm * 64 + mt * 16 + g + h * 8;
                if (grow < N_NODES) {
                    float v0 = fmaxf(acc[mt][nt][h * 2]     + bb0, 0.f);
                    float v1 = fmaxf(acc[mt][nt][h * 2 + 1] + bb1, 0.f);
                    float h0 = __half2float(__float2half_rn(v0));
                    float h1 = __half2float(__float2half_rn(v1));
                    long o = grow * 128 + (c >> 1);
                    g_hh[o] = pk2h(v0, v1);
                    g_hl[o] = pk2h(v0 - h0, v1 - h1);
                }
            }
        }
    }
}

// ======================= GEMM2 =======================
#define ST2 25600
#define SM2_BYTES (2 * ST2)
__device__ __forceinline__ void mlp2_fill(uint8_t* sm, int s, int kc, int tid, long grow0) {
    const uint32_t so = (uint32_t)s * ST2;
    #pragma unroll
    for (int it = 0; it < 4; it++) {
        int i = tid + it * 256;
        int row = i >> 3, arr = (i >> 2) & 1, c = i & 3;
        long grow = grow0 + row;
        const uint32_t* src = (arr ? g_hl : g_hh) + (grow < N_NODES ? grow * 128 : 0)
                              + kc * 16 + c * 4;
        uint32_t dst = smem_u32(sm) + so + (uint32_t)(arr * 10240 + row * 80 + c * 16);
        cpa16(dst, src, grow < N_NODES ? 16u : 0u);
    }
    if (tid < 256) {
        int n = tid >> 2, c = tid & 3;
        const uint32_t* src = (const uint32_t*)g_w2t + (long)n * 128 + kc * 16 + c * 4;
        uint32_t dst = smem_u32(sm) + so + (uint32_t)(20480 + n * 80 + c * 16);
        cpa16(dst, src, 16u);
    }
}
__global__ __launch_bounds__(256, 2)
void mlp2_kernel(const float* __restrict__ b2) {
    extern __shared__ uint8_t sm2[];
    const uint32_t sb = smem_u32(sm2);
    const int tid = threadIdx.x, lane = tid & 31, wid = tid >> 5;
    const int wm = wid >> 1, wn = wid & 1;
    const long grow0 = (long)blockIdx.x * 128;

    float acc[2][4][4];
    #pragma unroll
    for (int a = 0; a < 2; a++)
        #pragma unroll
        for (int b = 0; b < 4; b++)
            #pragma unroll
            for (int c = 0; c < 4; c++) acc[a][b][c] = 0.f;

    mlp2_fill(sm2, 0, 0, tid, grow0);
    cpa_commit();

    for (int kc = 0; kc < 8; kc++) {
        const int cur = kc & 1;
        if (kc + 1 < 8) { mlp2_fill(sm2, 1 - cur, kc + 1, tid, grow0); cpa_commit(); }
        if (kc + 1 < 8) cpa_wait1(); else cpa_wait0();
        __syncthreads();
        const uint32_t so = (uint32_t)cur * ST2;
        #pragma unroll
        for (int ks = 0; ks < 2; ks++) {
            const uint32_t colb = (uint32_t)((ks * 16 + (lane >> 4) * 8) * 2);
            uint32_t bb[2][4];
            #pragma unroll
            for (int g = 0; g < 2; g++) {
                int n = wn * 32 + g * 16 + (lane & 15);
                ldsm4(bb[g], sb + so + 20480 + (uint32_t)(n * 80) + colb);
            }
            #pragma unroll
            for (int mt = 0; mt < 2; mt++) {
                int r = wm * 32 + mt * 16 + (lane & 15);
                uint32_t ad = sb + so + (uint32_t)(r * 80) + colb;
                uint32_t ah[4], al[4];
                ldsm4(ah, ad);
                ldsm4(al, ad + 10240);
                #pragma unroll
                for (int g = 0; g < 2; g++) {
                    mma_f16(acc[mt][2 * g],     ah, bb[g][0], bb[g][2]);
                    mma_f16(acc[mt][2 * g],     al, bb[g][0], bb[g][2]);
                    mma_f16(acc[mt][2 * g + 1], ah, bb[g][1], bb[g][3]);
                    mma_f16(acc[mt][2 * g + 1], al, bb[g][1], bb[g][3]);
                }
            }
        }
        __syncthreads();
    }
    const int g = lane >> 2, t4 = lane & 3;
    #pragma unroll
    for (int mt = 0; mt < 2; mt++) {
        #pragma unroll
        for (int nt = 0; nt < 4; nt++) {
            int c = wn * 32 + nt * 8 + t4 * 2;
            float bb0 = __ldg(&b2[c]), bb1 = __ldg(&b2[c + 1]);
            #pragma unroll
            for (int h = 0; h < 2; h++) {
                long grow = grow0 + wm * 32 + mt * 16 + g + h * 8;
                if (grow < N_NODES) {
                    float2 o;
                    o.x = acc[mt][nt][h * 2]     + bb0;
                    o.y = acc[mt][nt][h * 2 + 1] + bb1;
                    *(float2*)(g_bufA + grow * 64 + c) = o;
                    g_c16A[grow * 32 + (c >> 1)] = __float22half2_rn(o);
                }
            }
        }
    }
}

// ---- SpMM: fp16 gather, fp32 state; 16 lanes/edge, 4-edge unroll for MLP ----
__device__ __forceinline__ void fma4h(float4& acc, uint2 p, float v) {
    float2 a0 = __half22float2(*(const __half2*)&p.x);
    float2 a1 = __half22float2(*(const __half2*)&p.y);
    acc.x = fmaf(v, a0.x, acc.x); acc.y = fmaf(v, a0.y, acc.y);
    acc.z = fmaf(v, a1.x, acc.z); acc.w = fmaf(v, a1.y, acc.w);
}
__device__ __forceinline__ float4 gather16(const __half2* __restrict__ tc16,
                                           int s, int e, int half, int q,
                                           const int* __restrict__ ecol,
                                           const float* __restrict__ eval) {
    float4 acc = make_float4(0.f, 0.f, 0.f, 0.f);
    int i = s + half;
    for (; i + 6 < e; i += 8) {
        int   c0 = __ldg(&ecol[i]),     c1 = __ldg(&ecol[i + 2]);
        int   c2 = __ldg(&ecol[i + 4]), c3 = __ldg(&ecol[i + 6]);
        float v0 = __ldg(&eval[i]),     v1 = __ldg(&eval[i + 2]);
        float v2 = __ldg(&eval[i + 4]), v3 = __ldg(&eval[i + 6]);
        uint2 p0 = *(const uint2*)(tc16 + (long)c0 * 32 + q * 2);
        uint2 p1 = *(const uint2*)(tc16 + (long)c1 * 32 + q * 2);
        uint2 p2 = *(const uint2*)(tc16 + (long)c2 * 32 + q * 2);
        uint2 p3 = *(const uint2*)(tc16 + (long)c3 * 32 + q * 2);
        fma4h(acc, p0, v0); fma4h(acc, p1, v1);
        fma4h(acc, p2, v2); fma4h(acc, p3, v3);
    }
    for (; i < e; i += 2) {
        int   c = __ldg(&ecol[i]);
        float v = __ldg(&eval[i]);
        uint2 p = *(const uint2*)(tc16 + (long)c * 32 + q * 2);
        fma4h(acc, p, v);
    }
    acc.x += __shfl_down_sync(0xffffffffu, acc.x, 16);
    acc.y += __shfl_down_sync(0xffffffffu, acc.y, 16);
    acc.z += __shfl_down_sync(0xffffffffu, acc.z, 16);
    acc.w += __shfl_down_sync(0xffffffffu, acc.w, 16);
    return acc;
}
__global__ __launch_bounds__(256)
void spmm_first(const int* __restrict__ ecol, const float* __restrict__ eval,
                const float* __restrict__ gamma, float* __restrict__ z) {
    int w = (blockIdx.x * 256 + threadIdx.x) >> 5;
    if (w >= N_NODES) return;
    int lane = threadIdx.x & 31, half = lane >> 4, q = lane & 15;
    int s = g_rowptr[w], e = g_rowptr[w + 1];
    float4 acc = gather16(g_c16A, s, e, half, q, ecol, eval);
    if (half == 0) {
        long o = (long)w * 16 + q;
        float g0 = __ldg(&gamma[0]), g1 = __ldg(&gamma[1]);
        float4 h4 = ((const float4*)g_bufA)[o];
        ((float4*)g_bufB)[o] = acc;
        g_c16B[(long)w * 32 + q * 2]     = __floats2half2_rn(acc.x, acc.y);
        g_c16B[(long)w * 32 + q * 2 + 1] = __floats2half2_rn(acc.z, acc.w);
        float4 zz;
        zz.x = g0 * h4.x + g1 * acc.x;
        zz.y = g0 * h4.y + g1 * acc.y;
        zz.z = g0 * h4.z + g1 * acc.z;
        zz.w = g0 * h4.w + g1 * acc.w;
        ((float4*)z)[o] = zz;
    }
}
__global__ __launch_bounds__(256)
void spmm_step(int swap, int k, const int* __restrict__ ecol,
               const float* __restrict__ eval, const float* __restrict__ gamma,
               float* __restrict__ z) {
    int w = (blockIdx.x * 256 + threadIdx.x) >> 5;
    if (w >= N_NODES) return;
    int lane = threadIdx.x & 31, half = lane >> 4, q = lane & 15;
    int s = g_rowptr[w], e = g_rowptr[w + 1];
    const __half2* tc16 = swap ? g_c16A : g_c16B;
    __half2*       wt16 = swap ? g_c16B : g_c16A;
    float*         pd   = swap ? g_bufB : g_bufA;
    float4 acc = gather16(tc16, s, e, half, q, ecol, eval);
    if (half == 0) {
        long o = (long)w * 16 + q;
        float gk = __ldg(&gamma[k]);
        float4 pv = ((const float4*)pd)[o];
        float4 tn;
        tn.x = 2.f * acc.x - pv.x; tn.y = 2.f * acc.y - pv.y;
        tn.z = 2.f * acc.z - pv.z; tn.w = 2.f * acc.w - pv.w;
        ((float4*)pd)[o] = tn;
        wt16[(long)w * 32 + q * 2]     = __floats2half2_rn(tn.x, tn.y);
        wt16[(long)w * 32 + q * 2 + 1] = __floats2half2_rn(tn.z, tn.w);
        float4 zz = ((float4*)z)[o];
        zz.x = fmaf(gk, tn.x, zz.x); zz.y = fmaf(gk, tn.y, zz.y);
        zz.z = fmaf(gk, tn.z, zz.z); zz.w = fmaf(gk, tn.w, zz.w);
        ((float4*)z)[o] = zz;
    }
}

// ---- launch ----
extern "C" void kernel_launch(void* const* d_in, const int* in_sizes, int n_in,
                              void* d_out, int out_size) {
    (void)in_sizes; (void)n_in; (void)out_size;
    const float* x     = (const float*)d_in[0];
    const int*   erow  = (const int*)  d_in[1];
    const int*   ecol  = (const int*)  d_in[2];
    const float* eval  = (const float*)d_in[3];
    const float* W1    = (const float*)d_in[4];
    const float* b1    = (const float*)d_in[5];
    const float* W2    = (const float*)d_in[6];
    const float* b2    = (const float*)d_in[7];
    const float* gamma = (const float*)d_in[8];
    float* z = (float*)d_out;

    cudaFuncSetAttribute(mlp1_kernel, cudaFuncAttributeMaxDynamicSharedMemorySize, SM1_BYTES);
    cudaFuncSetAttribute(mlp2_kernel, cudaFuncAttributeMaxDynamicSharedMemorySize, SM2_BYTES);

    prep_w<<<576, 256>>>(W1, W2);
    prep_x<<<(int)(((long)N_NODES * 256 + 255) / 256), 256>>>((const float2*)x);
    rowptr_kernel<<<392, 256>>>(erow);
    const int MT = (N_NODES + 127) / 128;   // 782
    mlp1_kernel<<<MT * 2, 256, SM1_BYTES>>>(b1);
    mlp2_kernel<<<MT, 256, SM2_BYTES>>>(b2);
    spmm_first<<<12500, 256>>>(ecol, eval, gamma, z);
    for (int k = 2; k <= 8; k++)
        spmm_step<<<12500, 256>>>(k & 1, k, ecol, eval, gamma, z);
}

// round 15
// speedup vs baseline: 1.3876x; 1.3876x over previous
#include <cuda_runtime.h>
#include <cuda_bf16.h>
#include <cuda_fp16.h>
#include <cstdint>

#define N_NODES 100000
#define N_EDGES 3200000
#define IN_DIM  512
#define HID     256
#define CLS     64

// ---- device scratch ----
__device__ __half g_w1t[HID * IN_DIM];            // W1^T fp16 [n=256][k=512]
__device__ __half g_w2t[CLS * HID];               // W2^T fp16 [n=64][k=256]
__device__ uint32_t g_xh[(size_t)N_NODES * 256];  // x fp16x2
__device__ uint32_t g_hh[(size_t)N_NODES * 128];  // H hi fp16x2
__device__ uint32_t g_hl[(size_t)N_NODES * 128];  // H lo fp16x2
__device__ float g_bufA[(size_t)N_NODES * CLS];   // fp32 state
__device__ float g_bufB[(size_t)N_NODES * CLS];
__device__ __half2 g_c16A[(size_t)N_NODES * 32];  // fp16 gather shadow
__device__ __half2 g_c16B[(size_t)N_NODES * 32];
__device__ int   g_rowptr[N_NODES + 1];

// ---- helpers ----
__device__ __forceinline__ uint32_t smem_u32(const void* p) {
    uint32_t a;
    asm("{ .reg .u64 t; cvta.to.shared.u64 t, %1; cvt.u32.u64 %0, t; }" : "=r"(a) : "l"(p));
    return a;
}
__device__ __forceinline__ uint32_t pk2h(float a, float b) {    // fp16x2
    uint16_t ha = __half_as_ushort(__float2half_rn(a));
    uint16_t hb = __half_as_ushort(__float2half_rn(b));
    return (uint32_t)ha | ((uint32_t)hb << 16);
}
__device__ __forceinline__ void ldsm4(uint32_t* r, uint32_t addr) {
    asm volatile("ldmatrix.sync.aligned.m8n8.x4.shared.b16 {%0,%1,%2,%3}, [%4];"
                 : "=r"(r[0]), "=r"(r[1]), "=r"(r[2]), "=r"(r[3]) : "r"(addr));
}
__device__ __forceinline__ void mma_f16(float* c, const uint32_t* a,
                                        uint32_t b0, uint32_t b1) {
    asm volatile(
        "mma.sync.aligned.m16n8k16.row.col.f32.f16.f16.f32 "
        "{%0,%1,%2,%3}, {%4,%5,%6,%7}, {%8,%9}, {%0,%1,%2,%3};"
        : "+f"(c[0]), "+f"(c[1]), "+f"(c[2]), "+f"(c[3])
        : "r"(a[0]), "r"(a[1]), "r"(a[2]), "r"(a[3]), "r"(b0), "r"(b1));
}
__device__ __forceinline__ void cpa16(uint32_t dst, const void* src, uint32_t sz) {
    asm volatile("cp.async.ca.shared.global [%0], [%1], 16, %2;"
                 :: "r"(dst), "l"(src), "r"(sz));
}
__device__ __forceinline__ void cpa_commit() { asm volatile("cp.async.commit_group;"); }
__device__ __forceinline__ void cpa_wait1()  { asm volatile("cp.async.wait_group 1;"); }
__device__ __forceinline__ void cpa_wait0()  { asm volatile("cp.async.wait_group 0;"); }

// ---- prep ----
__global__ void prep_w(const float* __restrict__ W1, const float* __restrict__ W2) {
    int idx = blockIdx.x * 256 + threadIdx.x;
    if (idx < HID * IN_DIM) {
        int n = idx >> 9, k = idx & 511;
        g_w1t[idx] = __float2half_rn(W1[k * HID + n]);
    }
    int j = idx - HID * IN_DIM;
    if (j >= 0 && j < CLS * HID) {
        int o = j >> 8, k = j & 255;
        g_w2t[j] = __float2half_rn(W2[k * CLS + o]);
    }
}
__global__ void prep_x(const float2* __restrict__ x2) {
    long i = (long)blockIdx.x * 256 + threadIdx.x;
    if (i >= (long)N_NODES * 256) return;
    float2 v = x2[i];
    g_xh[i] = pk2h(v.x, v.y);
}
__global__ void rowptr_kernel(const int* __restrict__ erow) {
    int r = blockIdx.x * 256 + threadIdx.x;
    if (r > N_NODES) return;
    int lo = 0, hi = N_EDGES;
    while (lo < hi) { int mid = (lo + hi) >> 1; if (erow[mid] < r) lo = mid + 1; else hi = mid; }
    g_rowptr[r] = lo;
}

// ======================= GEMM1 =======================
// H = relu(x@W1+b1), single-pass fp16. BM=128 BN=128, 2-stage cp.async, occ 2.
#define ST1 20480
#define SM1_BYTES (2 * ST1)
__device__ __forceinline__ void mlp1_fill(uint8_t* sm, int s, int kc, int tid,
                                          long grow0, int nbase) {
    const uint32_t so = (uint32_t)s * ST1;
    #pragma unroll
    for (int it = 0; it < 2; it++) {
        int i = tid + it * 256;
        int row = i >> 2, c = i & 3;
        long grow = grow0 + row;
        const uint32_t* src = g_xh + (grow < N_NODES ? grow * 256 : 0) + kc * 16 + c * 4;
        uint32_t dst = smem_u32(sm) + so + (uint32_t)(row * 80 + c * 16);
        cpa16(dst, src, grow < N_NODES ? 16u : 0u);
    }
    #pragma unroll
    for (int it = 0; it < 2; it++) {
        int i = tid + it * 256;
        int n = i >> 2, c = i & 3;
        const uint32_t* src = (const uint32_t*)g_w1t
                              + (long)(nbase + n) * 256 + kc * 16 + c * 4;
        uint32_t dst = smem_u32(sm) + so + (uint32_t)(10240 + n * 80 + c * 16);
        cpa16(dst, src, 16u);
    }
}
__global__ __launch_bounds__(256, 2)
void mlp1_kernel(const float* __restrict__ b1) {
    extern __shared__ uint8_t sm1[];
    const uint32_t sb = smem_u32(sm1);
    const int tid = threadIdx.x, lane = tid & 31, wid = tid >> 5;
    const int wm = wid >> 2, wn = wid & 3;
    const int mtile = blockIdx.x >> 1, nbase = (blockIdx.x & 1) * 128;
    const long grow0 = (long)mtile * 128;

    float acc[4][4][4];
    #pragma unroll
    for (int a = 0; a < 4; a++)
        #pragma unroll
        for (int b = 0; b < 4; b++)
            #pragma unroll
            for (int c = 0; c < 4; c++) acc[a][b][c] = 0.f;

    mlp1_fill(sm1, 0, 0, tid, grow0, nbase);
    cpa_commit();

    for (int kc = 0; kc < 16; kc++) {
        const int cur = kc & 1;
        if (kc + 1 < 16) { mlp1_fill(sm1, 1 - cur, kc + 1, tid, grow0, nbase); cpa_commit(); }
        if (kc + 1 < 16) cpa_wait1(); else cpa_wait0();
        __syncthreads();
        const uint32_t so = (uint32_t)cur * ST1;
        #pragma unroll
        for (int ks = 0; ks < 2; ks++) {
            const uint32_t colb = (uint32_t)((ks * 16 + (lane >> 4) * 8) * 2);
            uint32_t bb[2][4];
            #pragma unroll
            for (int g = 0; g < 2; g++) {
                int n = wn * 32 + g * 16 + (lane & 15);
                ldsm4(bb[g], sb + so + 10240 + (uint32_t)(n * 80) + colb);
            }
            #pragma unroll
            for (int mt = 0; mt < 4; mt++) {
                int r = wm * 64 + mt * 16 + (lane & 15);
                uint32_t ah[4];
                ldsm4(ah, sb + so + (uint32_t)(r * 80) + colb);
                #pragma unroll
                for (int g = 0; g < 2; g++) {
                    mma_f16(acc[mt][2 * g],     ah, bb[g][0], bb[g][2]);
                    mma_f16(acc[mt][2 * g + 1], ah, bb[g][1], bb[g][3]);
                }
            }
        }
        __syncthreads();
    }
    const int g = lane >> 2, t4 = lane & 3;
    #pragma unroll
    for (int mt = 0; mt < 4; mt++) {
        #pragma unroll
        for (int nt = 0; nt < 4; nt++) {
            int c = nbase + wn * 32 + nt * 8 + t4 * 2;
            float bb0 = __ldg(&b1[c]), bb1 = __ldg(&b1[c + 1]);
            #pragma unroll
            for (int h = 0; h < 2; h++) {
                long grow = grow0 + wm * 64 + mt * 16 + g + h * 8;
                if (grow < N_NODES) {
                    float v0 = fmaxf(acc[mt][nt][h * 2]     + bb0, 0.f);
                    float v1 = fmaxf(acc[mt][nt][h * 2 + 1] + bb1, 0.f);
                    float h0 = __half2float(__float2half_rn(v0));
                    float h1 = __half2float(__float2half_rn(v1));
                    long o = grow * 128 + (c >> 1);
                    g_hh[o] = pk2h(v0, v1);
                    g_hl[o] = pk2h(v0 - h0, v1 - h1);
                }
            }
        }
    }
}

// ======================= GEMM2 =======================
#define ST2 25600
#define SM2_BYTES (2 * ST2)
__device__ __forceinline__ void mlp2_fill(uint8_t* sm, int s, int kc, int tid, long grow0) {
    const uint32_t so = (uint32_t)s * ST2;
    #pragma unroll
    for (int it = 0; it < 4; it++) {
        int i = tid + it * 256;
        int row = i >> 3, arr = (i >> 2) & 1, c = i & 3;
        long grow = grow0 + row;
        const uint32_t* src = (arr ? g_hl : g_hh) + (grow < N_NODES ? grow * 128 : 0)
                              + kc * 16 + c * 4;
        uint32_t dst = smem_u32(sm) + so + (uint32_t)(arr * 10240 + row * 80 + c * 16);
        cpa16(dst, src, grow < N_NODES ? 16u : 0u);
    }
    if (tid < 256) {
        int n = tid >> 2, c = tid & 3;
        const uint32_t* src = (const uint32_t*)g_w2t + (long)n * 128 + kc * 16 + c * 4;
        uint32_t dst = smem_u32(sm) + so + (uint32_t)(20480 + n * 80 + c * 16);
        cpa16(dst, src, 16u);
    }
}
__global__ __launch_bounds__(256, 2)
void mlp2_kernel(const float* __restrict__ b2) {
    extern __shared__ uint8_t sm2[];
    const uint32_t sb = smem_u32(sm2);
    const int tid = threadIdx.x, lane = tid & 31, wid = tid >> 5;
    const int wm = wid >> 1, wn = wid & 1;
    const long grow0 = (long)blockIdx.x * 128;

    float acc[2][4][4];
    #pragma unroll
    for (int a = 0; a < 2; a++)
        #pragma unroll
        for (int b = 0; b < 4; b++)
            #pragma unroll
            for (int c = 0; c < 4; c++) acc[a][b][c] = 0.f;

    mlp2_fill(sm2, 0, 0, tid, grow0);
    cpa_commit();

    for (int kc = 0; kc < 8; kc++) {
        const int cur = kc & 1;
        if (kc + 1 < 8) { mlp2_fill(sm2, 1 - cur, kc + 1, tid, grow0); cpa_commit(); }
        if (kc + 1 < 8) cpa_wait1(); else cpa_wait0();
        __syncthreads();
        const uint32_t so = (uint32_t)cur * ST2;
        #pragma unroll
        for (int ks = 0; ks < 2; ks++) {
            const uint32_t colb = (uint32_t)((ks * 16 + (lane >> 4) * 8) * 2);
            uint32_t bb[2][4];
            #pragma unroll
            for (int g = 0; g < 2; g++) {
                int n = wn * 32 + g * 16 + (lane & 15);
                ldsm4(bb[g], sb + so + 20480 + (uint32_t)(n * 80) + colb);
            }
            #pragma unroll
            for (int mt = 0; mt < 2; mt++) {
                int r = wm * 32 + mt * 16 + (lane & 15);
                uint32_t ad = sb + so + (uint32_t)(r * 80) + colb;
                uint32_t ah[4], al[4];
                ldsm4(ah, ad);
                ldsm4(al, ad + 10240);
                #pragma unroll
                for (int g = 0; g < 2; g++) {
                    mma_f16(acc[mt][2 * g],     ah, bb[g][0], bb[g][2]);
                    mma_f16(acc[mt][2 * g],     al, bb[g][0], bb[g][2]);
                    mma_f16(acc[mt][2 * g + 1], ah, bb[g][1], bb[g][3]);
                    mma_f16(acc[mt][2 * g + 1], al, bb[g][1], bb[g][3]);
                }
            }
        }
        __syncthreads();
    }
    const int g = lane >> 2, t4 = lane & 3;
    #pragma unroll
    for (int mt = 0; mt < 2; mt++) {
        #pragma unroll
        for (int nt = 0; nt < 4; nt++) {
            int c = wn * 32 + nt * 8 + t4 * 2;
            float bb0 = __ldg(&b2[c]), bb1 = __ldg(&b2[c + 1]);
            #pragma unroll
            for (int h = 0; h < 2; h++) {
                long grow = grow0 + wm * 32 + mt * 16 + g + h * 8;
                if (grow < N_NODES) {
                    float2 o;
                    o.x = acc[mt][nt][h * 2]     + bb0;
                    o.y = acc[mt][nt][h * 2 + 1] + bb1;
                    *(float2*)(g_bufA + grow * 64 + c) = o;
                    g_c16A[grow * 32 + (c >> 1)] = __float22half2_rn(o);
                }
            }
        }
    }
}

// ---- SpMM: fp16 gather, fp32 state ----
__device__ __forceinline__ float4 gather16(const __half2* __restrict__ tc16,
                                           int s, int e, int half, int q,
                                           const int* __restrict__ ecol,
                                           const float* __restrict__ eval) {
    float4 acc = make_float4(0.f, 0.f, 0.f, 0.f);
    int i = s + half;
    for (; i + 2 < e; i += 4) {
        int   c0 = __ldg(&ecol[i]),     c1 = __ldg(&ecol[i + 2]);
        float v0 = __ldg(&eval[i]),     v1 = __ldg(&eval[i + 2]);
        uint2 p0 = *(const uint2*)(tc16 + (long)c0 * 32 + q * 2);
        uint2 p1 = *(const uint2*)(tc16 + (long)c1 * 32 + q * 2);
        float2 a0 = __half22float2(*(const __half2*)&p0.x);
        float2 a1 = __half22float2(*(const __half2*)&p0.y);
        float2 b0 = __half22float2(*(const __half2*)&p1.x);
        float2 b1 = __half22float2(*(const __half2*)&p1.y);
        acc.x = fmaf(v0, a0.x, acc.x); acc.y = fmaf(v0, a0.y, acc.y);
        acc.z = fmaf(v0, a1.x, acc.z); acc.w = fmaf(v0, a1.y, acc.w);
        acc.x = fmaf(v1, b0.x, acc.x); acc.y = fmaf(v1, b0.y, acc.y);
        acc.z = fmaf(v1, b1.x, acc.z); acc.w = fmaf(v1, b1.y, acc.w);
    }
    for (; i < e; i += 2) {
        int   c = __ldg(&ecol[i]);
        float v = __ldg(&eval[i]);
        uint2 p = *(const uint2*)(tc16 + (long)c * 32 + q * 2);
        float2 a0 = __half22float2(*(const __half2*)&p.x);
        float2 a1 = __half22float2(*(const __half2*)&p.y);
        acc.x = fmaf(v, a0.x, acc.x); acc.y = fmaf(v, a0.y, acc.y);
        acc.z = fmaf(v, a1.x, acc.z); acc.w = fmaf(v, a1.y, acc.w);
    }
    acc.x += __shfl_down_sync(0xffffffffu, acc.x, 16);
    acc.y += __shfl_down_sync(0xffffffffu, acc.y, 16);
    acc.z += __shfl_down_sync(0xffffffffu, acc.z, 16);
    acc.w += __shfl_down_sync(0xffffffffu, acc.w, 16);
    return acc;
}
__global__ __launch_bounds__(256)
void spmm_first(const int* __restrict__ ecol, const float* __restrict__ eval,
                const float* __restrict__ gamma, float* __restrict__ z) {
    int w = (blockIdx.x * 256 + threadIdx.x) >> 5;
    if (w >= N_NODES) return;
    int lane = threadIdx.x & 31, half = lane >> 4, q = lane & 15;
    int s = g_rowptr[w], e = g_rowptr[w + 1];
    float4 acc = gather16(g_c16A, s, e, half, q, ecol, eval);
    if (half == 0) {
        long o = (long)w * 16 + q;
        float g0 = __ldg(&gamma[0]), g1 = __ldg(&gamma[1]);
        float4 h4 = ((const float4*)g_bufA)[o];
        ((float4*)g_bufB)[o] = acc;
        g_c16B[(long)w * 32 + q * 2]     = __floats2half2_rn(acc.x, acc.y);
        g_c16B[(long)w * 32 + q * 2 + 1] = __floats2half2_rn(acc.z, acc.w);
        float4 zz;
        zz.x = g0 * h4.x + g1 * acc.x;
        zz.y = g0 * h4.y + g1 * acc.y;
        zz.z = g0 * h4.z + g1 * acc.z;
        zz.w = g0 * h4.w + g1 * acc.w;
        ((float4*)z)[o] = zz;
    }
}
__global__ __launch_bounds__(256)
void spmm_step(int swap, int k, const int* __restrict__ ecol,
               const float* __restrict__ eval, const float* __restrict__ gamma,
               float* __restrict__ z) {
    int w = (blockIdx.x * 256 + threadIdx.x) >> 5;
    if (w >= N_NODES) return;
    int lane = threadIdx.x & 31, half = lane >> 4, q = lane & 15;
    int s = g_rowptr[w], e = g_rowptr[w + 1];
    const __half2* tc16 = swap ? g_c16A : g_c16B;
    __half2*       wt16 = swap ? g_c16B : g_c16A;
    float*         pd   = swap ? g_bufB : g_bufA;
    float4 acc = gather16(tc16, s, e, half, q, ecol, eval);
    if (half == 0) {
        long o = (long)w * 16 + q;
        float gk = __ldg(&gamma[k]);
        float4 pv = ((const float4*)pd)[o];
        float4 tn;
        tn.x = 2.f * acc.x - pv.x; tn.y = 2.f * acc.y - pv.y;
        tn.z = 2.f * acc.z - pv.z; tn.w = 2.f * acc.w - pv.w;
        ((float4*)pd)[o] = tn;
        wt16[(long)w * 32 + q * 2]     = __floats2half2_rn(tn.x, tn.y);
        wt16[(long)w * 32 + q * 2 + 1] = __floats2half2_rn(tn.z, tn.w);
        float4 zz = ((float4*)z)[o];
        zz.x = fmaf(gk, tn.x, zz.x); zz.y = fmaf(gk, tn.y, zz.y);
        zz.z = fmaf(gk, tn.z, zz.z); zz.w = fmaf(gk, tn.w, zz.w);
        ((float4*)z)[o] = zz;
    }
}

// ---- launch ----
extern "C" void kernel_launch(void* const* d_in, const int* in_sizes, int n_in,
                              void* d_out, int out_size) {
    (void)in_sizes; (void)n_in; (void)out_size;
    const float* x     = (const float*)d_in[0];
    const int*   erow  = (const int*)  d_in[1];
    const int*   ecol  = (const int*)  d_in[2];
    const float* eval  = (const float*)d_in[3];
    const float* W1    = (const float*)d_in[4];
    const float* b1    = (const float*)d_in[5];
    const float* W2    = (const float*)d_in[6];
    const float* b2    = (const float*)d_in[7];
    const float* gamma = (const float*)d_in[8];
    float* z = (float*)d_out;

    cudaFuncSetAttribute(mlp1_kernel, cudaFuncAttributeMaxDynamicSharedMemorySize, SM1_BYTES);
    cudaFuncSetAttribute(mlp2_kernel, cudaFuncAttributeMaxDynamicSharedMemorySize, SM2_BYTES);

    prep_w<<<576, 256>>>(W1, W2);
    prep_x<<<(int)(((long)N_NODES * 256 + 255) / 256), 256>>>((const float2*)x);
    rowptr_kernel<<<392, 256>>>(erow);
    const int MT = (N_NODES + 127) / 128;   // 782
    mlp1_kernel<<<MT * 2, 256, SM1_BYTES>>>(b1);
    mlp2_kernel<<<MT, 256, SM2_BYTES>>>(b2);
    spmm_first<<<12500, 256>>>(ecol, eval, gamma, z);
    for (int k = 2; k <= 8; k++)
        spmm_step<<<12500, 256>>>(k & 1, k, ecol, eval, gamma, z);
}

// round 17
// speedup vs baseline: 1.3945x; 1.0050x over previous
#include <cuda_runtime.h>
#include <cuda_bf16.h>
#include <cuda_fp16.h>
#include <cstdint>

#define N_NODES 100000
#define N_EDGES 3200000
#define IN_DIM  512
#define HID     256
#define CLS     64

// ---- device scratch ----
__device__ __half g_w1t[HID * IN_DIM];            // W1^T fp16 [n=256][k=512]
__device__ __half g_w2t[CLS * HID];               // W2^T fp16 [n=64][k=256]
__device__ uint32_t g_xh[(size_t)N_NODES * 256];  // x fp16x2
__device__ uint32_t g_hh[(size_t)N_NODES * 128];  // H hi fp16x2
__device__ uint32_t g_hl[(size_t)N_NODES * 128];  // H lo fp16x2
__device__ float g_bufA[(size_t)N_NODES * CLS];   // fp32 state
__device__ float g_bufB[(size_t)N_NODES * CLS];
__device__ __half2 g_c16A[(size_t)N_NODES * 32];  // fp16 gather shadow
__device__ __half2 g_c16B[(size_t)N_NODES * 32];
__device__ int   g_rowptr[N_NODES + 1];

// ---- helpers ----
__device__ __forceinline__ uint32_t smem_u32(const void* p) {
    uint32_t a;
    asm("{ .reg .u64 t; cvta.to.shared.u64 t, %1; cvt.u32.u64 %0, t; }" : "=r"(a) : "l"(p));
    return a;
}
__device__ __forceinline__ uint32_t pk2h(float a, float b) {    // fp16x2
    uint16_t ha = __half_as_ushort(__float2half_rn(a));
    uint16_t hb = __half_as_ushort(__float2half_rn(b));
    return (uint32_t)ha | ((uint32_t)hb << 16);
}
__device__ __forceinline__ void ldsm4(uint32_t* r, uint32_t addr) {
    asm volatile("ldmatrix.sync.aligned.m8n8.x4.shared.b16 {%0,%1,%2,%3}, [%4];"
                 : "=r"(r[0]), "=r"(r[1]), "=r"(r[2]), "=r"(r[3]) : "r"(addr));
}
__device__ __forceinline__ void mma_f16(float* c, const uint32_t* a,
                                        uint32_t b0, uint32_t b1) {
    asm volatile(
        "mma.sync.aligned.m16n8k16.row.col.f32.f16.f16.f32 "
        "{%0,%1,%2,%3}, {%4,%5,%6,%7}, {%8,%9}, {%0,%1,%2,%3};"
        : "+f"(c[0]), "+f"(c[1]), "+f"(c[2]), "+f"(c[3])
        : "r"(a[0]), "r"(a[1]), "r"(a[2]), "r"(a[3]), "r"(b0), "r"(b1));
}
__device__ __forceinline__ void cpa16(uint32_t dst, const void* src, uint32_t sz) {
    asm volatile("cp.async.ca.shared.global [%0], [%1], 16, %2;"
                 :: "r"(dst), "l"(src), "r"(sz));
}
__device__ __forceinline__ void cpa_commit() { asm volatile("cp.async.commit_group;"); }
__device__ __forceinline__ void cpa_wait1()  { asm volatile("cp.async.wait_group 1;"); }
__device__ __forceinline__ void cpa_wait0()  { asm volatile("cp.async.wait_group 0;"); }

// ---- prep ----
__global__ void prep_w(const float* __restrict__ W1, const float* __restrict__ W2) {
    int idx = blockIdx.x * 256 + threadIdx.x;
    if (idx < HID * IN_DIM) {
        int n = idx >> 9, k = idx & 511;
        g_w1t[idx] = __float2half_rn(W1[k * HID + n]);
    }
    int j = idx - HID * IN_DIM;
    if (j >= 0 && j < CLS * HID) {
        int o = j >> 8, k = j & 255;
        g_w2t[j] = __float2half_rn(W2[k * CLS + o]);
    }
}
__global__ void prep_x(const float2* __restrict__ x2) {
    long i = (long)blockIdx.x * 256 + threadIdx.x;
    if (i >= (long)N_NODES * 256) return;
    float2 v = x2[i];
    g_xh[i] = pk2h(v.x, v.y);
}
__global__ void rowptr_kernel(const int* __restrict__ erow) {
    int r = blockIdx.x * 256 + threadIdx.x;
    if (r > N_NODES) return;
    int lo = 0, hi = N_EDGES;
    while (lo < hi) { int mid = (lo + hi) >> 1; if (erow[mid] < r) lo = mid + 1; else hi = mid; }
    g_rowptr[r] = lo;
}

// ======================= GEMM1 =======================
// H = relu(x@W1+b1), single-pass fp16. BM=128 BN=128, 2-stage cp.async, occ 2.
#define ST1 20480
#define SM1_BYTES (2 * ST1)
__device__ __forceinline__ void mlp1_fill(uint8_t* sm, int s, int kc, int tid,
                                          long grow0, int nbase) {
    const uint32_t so = (uint32_t)s * ST1;
    #pragma unroll
    for (int it = 0; it < 2; it++) {
        int i = tid + it * 256;
        int row = i >> 2, c = i & 3;
        long grow = grow0 + row;
        const uint32_t* src = g_xh + (grow < N_NODES ? grow * 256 : 0) + kc * 16 + c * 4;
        uint32_t dst = smem_u32(sm) + so + (uint32_t)(row * 80 + c * 16);
        cpa16(dst, src, grow < N_NODES ? 16u : 0u);
    }
    #pragma unroll
    for (int it = 0; it < 2; it++) {
        int i = tid + it * 256;
        int n = i >> 2, c = i & 3;
        const uint32_t* src = (const uint32_t*)g_w1t
                              + (long)(nbase + n) * 256 + kc * 16 + c * 4;
        uint32_t dst = smem_u32(sm) + so + (uint32_t)(10240 + n * 80 + c * 16);
        cpa16(dst, src, 16u);
    }
}
__global__ __launch_bounds__(256, 2)
void mlp1_kernel(const float* __restrict__ b1) {
    extern __shared__ uint8_t sm1[];
    const uint32_t sb = smem_u32(sm1);
    const int tid = threadIdx.x, lane = tid & 31, wid = tid >> 5;
    const int wm = wid >> 2, wn = wid & 3;
    const int mtile = blockIdx.x >> 1, nbase = (blockIdx.x & 1) * 128;
    const long grow0 = (long)mtile * 128;

    float acc[4][4][4];
    #pragma unroll
    for (int a = 0; a < 4; a++)
        #pragma unroll
        for (int b = 0; b < 4; b++)
            #pragma unroll
            for (int c = 0; c < 4; c++) acc[a][b][c] = 0.f;

    mlp1_fill(sm1, 0, 0, tid, grow0, nbase);
    cpa_commit();

    for (int kc = 0; kc < 16; kc++) {
        const int cur = kc & 1;
        if (kc + 1 < 16) { mlp1_fill(sm1, 1 - cur, kc + 1, tid, grow0, nbase); cpa_commit(); }
        if (kc + 1 < 16) cpa_wait1(); else cpa_wait0();
        __syncthreads();
        const uint32_t so = (uint32_t)cur * ST1;
        #pragma unroll
        for (int ks = 0; ks < 2; ks++) {
            const uint32_t colb = (uint32_t)((ks * 16 + (lane >> 4) * 8) * 2);
            uint32_t bb[2][4];
            #pragma unroll
            for (int g = 0; g < 2; g++) {
                int n = wn * 32 + g * 16 + (lane & 15);
                ldsm4(bb[g], sb + so + 10240 + (uint32_t)(n * 80) + colb);
            }
            #pragma unroll
            for (int mt = 0; mt < 4; mt++) {
                int r = wm * 64 + mt * 16 + (lane & 15);
                uint32_t ah[4];
                ldsm4(ah, sb + so + (uint32_t)(r * 80) + colb);
                #pragma unroll
                for (int g = 0; g < 2; g++) {
                    mma_f16(acc[mt][2 * g],     ah, bb[g][0], bb[g][2]);
                    mma_f16(acc[mt][2 * g + 1], ah, bb[g][1], bb[g][3]);
                }
            }
        }
        __syncthreads();
    }
    const int g = lane >> 2, t4 = lane & 3;
    #pragma unroll
    for (int mt = 0; mt < 4; mt++) {
        #pragma unroll
        for (int nt = 0; nt < 4; nt++) {
            int c = nbase + wn * 32 + nt * 8 + t4 * 2;
            float bb0 = __ldg(&b1[c]), bb1 = __ldg(&b1[c + 1]);
            #pragma unroll
            for (int h = 0; h < 2; h++) {
                long grow = grow0 + wm * 64 + mt * 16 + g + h * 8;
                if (grow < N_NODES) {
                    float v0 = fmaxf(acc[mt][nt][h * 2]     + bb0, 0.f);
                    float v1 = fmaxf(acc[mt][nt][h * 2 + 1] + bb1, 0.f);
                    float h0 = __half2float(__float2half_rn(v0));
                    float h1 = __half2float(__float2half_rn(v1));
                    long o = grow * 128 + (c >> 1);
                    g_hh[o] = pk2h(v0, v1);
                    g_hl[o] = pk2h(v0 - h0, v1 - h1);
                }
            }
        }
    }
}

// ======================= GEMM2 =======================
#define ST2 25600
#define SM2_BYTES (2 * ST2)
__device__ __forceinline__ void mlp2_fill(uint8_t* sm, int s, int kc, int tid, long grow0) {
    const uint32_t so = (uint32_t)s * ST2;
    #pragma unroll
    for (int it = 0; it < 4; it++) {
        int i = tid + it * 256;
        int row = i >> 3, arr = (i >> 2) & 1, c = i & 3;
        long grow = grow0 + row;
        const uint32_t* src = (arr ? g_hl : g_hh) + (grow < N_NODES ? grow * 128 : 0)
                              + kc * 16 + c * 4;
        uint32_t dst = smem_u32(sm) + so + (uint32_t)(arr * 10240 + row * 80 + c * 16);
        cpa16(dst, src, grow < N_NODES ? 16u : 0u);
    }
    if (tid < 256) {
        int n = tid >> 2, c = tid & 3;
        const uint32_t* src = (const uint32_t*)g_w2t + (long)n * 128 + kc * 16 + c * 4;
        uint32_t dst = smem_u32(sm) + so + (uint32_t)(20480 + n * 80 + c * 16);
        cpa16(dst, src, 16u);
    }
}
__global__ __launch_bounds__(256, 2)
void mlp2_kernel(const float* __restrict__ b2) {
    extern __shared__ uint8_t sm2[];
    const uint32_t sb = smem_u32(sm2);
    const int tid = threadIdx.x, lane = tid & 31, wid = tid >> 5;
    const int wm = wid >> 1, wn = wid & 1;
    const long grow0 = (long)blockIdx.x * 128;

    float acc[2][4][4];
    #pragma unroll
    for (int a = 0; a < 2; a++)
        #pragma unroll
        for (int b = 0; b < 4; b++)
            #pragma unroll
            for (int c = 0; c < 4; c++) acc[a][b][c] = 0.f;

    mlp2_fill(sm2, 0, 0, tid, grow0);
    cpa_commit();

    for (int kc = 0; kc < 8; kc++) {
        const int cur = kc & 1;
        if (kc + 1 < 8) { mlp2_fill(sm2, 1 - cur, kc + 1, tid, grow0); cpa_commit(); }
        if (kc + 1 < 8) cpa_wait1(); else cpa_wait0();
        __syncthreads();
        const uint32_t so = (uint32_t)cur * ST2;
        #pragma unroll
        for (int ks = 0; ks < 2; ks++) {
            const uint32_t colb = (uint32_t)((ks * 16 + (lane >> 4) * 8) * 2);
            uint32_t bb[2][4];
            #pragma unroll
            for (int g = 0; g < 2; g++) {
                int n = wn * 32 + g * 16 + (lane & 15);
                ldsm4(bb[g], sb + so + 20480 + (uint32_t)(n * 80) + colb);
            }
            #pragma unroll
            for (int mt = 0; mt < 2; mt++) {
                int r = wm * 32 + mt * 16 + (lane & 15);
                uint32_t ad = sb + so + (uint32_t)(r * 80) + colb;
                uint32_t ah[4], al[4];
                ldsm4(ah, ad);
                ldsm4(al, ad + 10240);
                #pragma unroll
                for (int g = 0; g < 2; g++) {
                    mma_f16(acc[mt][2 * g],     ah, bb[g][0], bb[g][2]);
                    mma_f16(acc[mt][2 * g],     al, bb[g][0], bb[g][2]);
                    mma_f16(acc[mt][2 * g + 1], ah, bb[g][1], bb[g][3]);
                    mma_f16(acc[mt][2 * g + 1], al, bb[g][1], bb[g][3]);
                }
            }
        }
        __syncthreads();
    }
    const int g = lane >> 2, t4 = lane & 3;
    #pragma unroll
    for (int mt = 0; mt < 2; mt++) {
        #pragma unroll
        for (int nt = 0; nt < 4; nt++) {
            int c = wn * 32 + nt * 8 + t4 * 2;
            float bb0 = __ldg(&b2[c]), bb1 = __ldg(&b2[c + 1]);
            #pragma unroll
            for (int h = 0; h < 2; h++) {
                long grow = grow0 + wm * 32 + mt * 16 + g + h * 8;
                if (grow < N_NODES) {
                    float2 o;
                    o.x = acc[mt][nt][h * 2]     + bb0;
                    o.y = acc[mt][nt][h * 2 + 1] + bb1;
                    *(float2*)(g_bufA + grow * 64 + c) = o;
                    g_c16A[grow * 32 + (c >> 1)] = __float22half2_rn(o);
                }
            }
        }
    }
}

// ---- SpMM: fp16 gather, fp32 state; 16 lanes/edge, 4-edge unroll for MLP ----
__device__ __forceinline__ void fma4h(float4& acc, uint2 p, float v) {
    float2 a0 = __half22float2(*(const __half2*)&p.x);
    float2 a1 = __half22float2(*(const __half2*)&p.y);
    acc.x = fmaf(v, a0.x, acc.x); acc.y = fmaf(v, a0.y, acc.y);
    acc.z = fmaf(v, a1.x, acc.z); acc.w = fmaf(v, a1.y, acc.w);
}
__device__ __forceinline__ float4 gather16(const __half2* __restrict__ tc16,
                                           int s, int e, int half, int q,
                                           const int* __restrict__ ecol,
                                           const float* __restrict__ eval) {
    float4 acc = make_float4(0.f, 0.f, 0.f, 0.f);
    int i = s + half;
    for (; i + 6 < e; i += 8) {
        int   c0 = __ldg(&ecol[i]),     c1 = __ldg(&ecol[i + 2]);
        int   c2 = __ldg(&ecol[i + 4]), c3 = __ldg(&ecol[i + 6]);
        float v0 = __ldg(&eval[i]),     v1 = __ldg(&eval[i + 2]);
        float v2 = __ldg(&eval[i + 4]), v3 = __ldg(&eval[i + 6]);
        uint2 p0 = *(const uint2*)(tc16 + (long)c0 * 32 + q * 2);
        uint2 p1 = *(const uint2*)(tc16 + (long)c1 * 32 + q * 2);
        uint2 p2 = *(const uint2*)(tc16 + (long)c2 * 32 + q * 2);
        uint2 p3 = *(const uint2*)(tc16 + (long)c3 * 32 + q * 2);
        fma4h(acc, p0, v0); fma4h(acc, p1, v1);
        fma4h(acc, p2, v2); fma4h(acc, p3, v3);
    }
    for (; i < e; i += 2) {
        int   c = __ldg(&ecol[i]);
        float v = __ldg(&eval[i]);
        uint2 p = *(const uint2*)(tc16 + (long)c * 32 + q * 2);
        fma4h(acc, p, v);
    }
    acc.x += __shfl_down_sync(0xffffffffu, acc.x, 16);
    acc.y += __shfl_down_sync(0xffffffffu, acc.y, 16);
    acc.z += __shfl_down_sync(0xffffffffu, acc.z, 16);
    acc.w += __shfl_down_sync(0xffffffffu, acc.w, 16);
    return acc;
}
__global__ __launch_bounds__(256)
void spmm_first(const int* __restrict__ ecol, const float* __restrict__ eval,
                const float* __restrict__ gamma, float* __restrict__ z) {
    int w = (blockIdx.x * 256 + threadIdx.x) >> 5;
    if (w >= N_NODES) return;
    int lane = threadIdx.x & 31, half = lane >> 4, q = lane & 15;
    int s = g_rowptr[w], e = g_rowptr[w + 1];
    float4 acc = gather16(g_c16A, s, e, half, q, ecol, eval);
    if (half == 0) {
        long o = (long)w * 16 + q;
        float g0 = __ldg(&gamma[0]), g1 = __ldg(&gamma[1]);
        float4 h4 = ((const float4*)g_bufA)[o];
        ((float4*)g_bufB)[o] = acc;
        g_c16B[(long)w * 32 + q * 2]     = __floats2half2_rn(acc.x, acc.y);
        g_c16B[(long)w * 32 + q * 2 + 1] = __floats2half2_rn(acc.z, acc.w);
        float4 zz;
        zz.x = g0 * h4.x + g1 * acc.x;
        zz.y = g0 * h4.y + g1 * acc.y;
        zz.z = g0 * h4.z + g1 * acc.z;
        zz.w = g0 * h4.w + g1 * acc.w;
        ((float4*)z)[o] = zz;
    }
}
__global__ __launch_bounds__(256)
void spmm_step(int swap, int k, const int* __restrict__ ecol,
               const float* __restrict__ eval, const float* __restrict__ gamma,
               float* __restrict__ z) {
    int w = (blockIdx.x * 256 + threadIdx.x) >> 5;
    if (w >= N_NODES) return;
    int lane = threadIdx.x & 31, half = lane >> 4, q = lane & 15;
    int s = g_rowptr[w], e = g_rowptr[w + 1];
    const __half2* tc16 = swap ? g_c16A : g_c16B;
    __half2*       wt16 = swap ? g_c16B : g_c16A;
    float*         pd   = swap ? g_bufB : g_bufA;
    float4 acc = gather16(tc16, s, e, half, q, ecol, eval);
    if (half == 0) {
        long o = (long)w * 16 + q;
        float gk = __ldg(&gamma[k]);
        float4 pv = ((const float4*)pd)[o];
        float4 tn;
        tn.x = 2.f * acc.x - pv.x; tn.y = 2.f * acc.y - pv.y;
        tn.z = 2.f * acc.z - pv.z; tn.w = 2.f * acc.w - pv.w;
        ((float4*)pd)[o] = tn;
        wt16[(long)w * 32 + q * 2]     = __floats2half2_rn(tn.x, tn.y);
        wt16[(long)w * 32 + q * 2 + 1] = __floats2half2_rn(tn.z, tn.w);
        float4 zz = ((float4*)z)[o];
        zz.x = fmaf(gk, tn.x, zz.x); zz.y = fmaf(gk, tn.y, zz.y);
        zz.z = fmaf(gk, tn.z, zz.z); zz.w = fmaf(gk, tn.w, zz.w);
        ((float4*)z)[o] = zz;
    }
}

// ---- launch ----
extern "C" void kernel_launch(void* const* d_in, const int* in_sizes, int n_in,
                              void* d_out, int out_size) {
    (void)in_sizes; (void)n_in; (void)out_size;
    const float* x     = (const float*)d_in[0];
    const int*   erow  = (const int*)  d_in[1];
    const int*   ecol  = (const int*)  d_in[2];
    const float* eval  = (const float*)d_in[3];
    const float* W1    = (const float*)d_in[4];
    const float* b1    = (const float*)d_in[5];
    const float* W2    = (const float*)d_in[6];
    const float* b2    = (const float*)d_in[7];
    const float* gamma = (const float*)d_in[8];
    float* z = (float*)d_out;

    cudaFuncSetAttribute(mlp1_kernel, cudaFuncAttributeMaxDynamicSharedMemorySize, SM1_BYTES);
    cudaFuncSetAttribute(mlp2_kernel, cudaFuncAttributeMaxDynamicSharedMemorySize, SM2_BYTES);

    prep_w<<<576, 256>>>(W1, W2);
    prep_x<<<(int)(((long)N_NODES * 256 + 255) / 256), 256>>>((const float2*)x);
    rowptr_kernel<<<392, 256>>>(erow);
    const int MT = (N_NODES + 127) / 128;   // 782
    mlp1_kernel<<<MT * 2, 256, SM1_BYTES>>>(b1);
    mlp2_kernel<<<MT, 256, SM2_BYTES>>>(b2);
    spmm_first<<<12500, 256>>>(ecol, eval, gamma, z);
    for (int k = 2; k <= 8; k++)
        spmm_step<<<12500, 256>>>(k & 1, k, ecol, eval, gamma, z);
}